// round 10
// baseline (speedup 1.0000x reference)
#include <cuda_runtime.h>

#define NTHREADS 256
#define TLEN 4096

// bank swizzle: conflict-free for strides 512/64/8/1 (verified per half-warp)
#define PH(e) ((e) ^ ((((unsigned)(e))>>3)&7u) ^ (((((unsigned)(e))>>6)&1u)<<3))

__device__ float4 g_masks_br[TLEN];  // masks at digit-reversed position, 1/4096 folded
__device__ float2 g_tw512[512];      // W4096^j
__device__ float2 g_t8[64];          // W4096^(8j)  = W512^j
__device__ float2 g_t64[8];          // W4096^(64j) = W64^j

struct __align__(16) Smem {
    float2 buf0[TLEN];     // Y1 path -> modes01 (natural, PH layout)
    float2 buf1[TLEN];     // spectrum park, then Y2 path -> mode2 in .x
    float2 t8[64];
    float2 t64[8];
    int    hist[8][36];
    float  red[8][20];
    float  totals[20];
    int    cnt[36];
    float  xnyq;
};

__device__ __forceinline__ float2 cadd(float2 a, float2 b){ return make_float2(a.x+b.x, a.y+b.y); }
__device__ __forceinline__ float2 csub(float2 a, float2 b){ return make_float2(a.x-b.x, a.y-b.y); }
__device__ __forceinline__ float2 cmul(float2 a, float2 b){
    return make_float2(fmaf(a.x,b.x,-a.y*b.y), fmaf(a.x,b.y, a.y*b.x));
}
__device__ __forceinline__ float2 conj2(float2 a){ return make_float2(a.x, -a.y); }

__global__ void init_tables()
{
    int j = blockIdx.x * blockDim.x + threadIdx.x;   // 0..4095
    float sv, cv;
    if (j < 512) {
        sincospif(-(float)j * (1.0f/2048.0f), &sv, &cv);  // -2pi j/4096
        g_tw512[j] = make_float2(cv, sv);
    }
    if (j < 64) {
        sincospif(-(float)j * (1.0f/256.0f), &sv, &cv);   // -2pi 8j/4096
        g_t8[j] = make_float2(cv, sv);
    }
    if (j < 8) {
        sincospif(-(float)j * (1.0f/32.0f), &sv, &cv);    // -2pi 64j/4096
        g_t64[j] = make_float2(cv, sv);
    }
    // frequency bin at digit-reversed position j (4 base-8 digits)
    int K = ((j&7)<<9) | (((j>>3)&7)<<6) | (((j>>6)&7)<<3) | ((j>>9)&7);
    float f = (float)((K < 2048) ? K : (K - 4096)) * (1.0f/4096.0f);
    const float h = 0.5f * (1.0f/4096.0f);
    float u;
    u = f + 0.5f; float a0 = expf(-12.5f*u*u);
    u = f - 0.5f; float a1 = expf(-12.5f*u*u);
    u = f - 0.3f; float b0 = expf(-12.5f*u*u);
    u = f + 0.3f; float b1 = expf(-12.5f*u*u);
    u = f - 0.1f; float c0 = expf(-12.5f*u*u);
    u = f + 0.1f; float c1 = expf(-12.5f*u*u);
    g_masks_br[j] = make_float4(h*(a0+a1), h*(b0+b1), h*(c0+c1), 0.f);
}

// In-place DFT-8: x[r] <- sum_n x[n] * W8^(+-rn)
template<bool INV>
__device__ __forceinline__ void dft8(float2 x[8])
{
    float2 t0=cadd(x[0],x[4]), t1=cadd(x[1],x[5]), t2=cadd(x[2],x[6]), t3=cadd(x[3],x[7]);
    float2 u0=csub(x[0],x[4]), u1=csub(x[1],x[5]), u2=csub(x[2],x[6]), u3=csub(x[3],x[7]);
    const float C8 = 0.70710678118654752f;
    const float2 om  = INV ? make_float2( C8,  C8) : make_float2( C8, -C8);
    const float2 om3 = INV ? make_float2(-C8,  C8) : make_float2(-C8, -C8);
    float2 v1 = cmul(u1, om);
    float2 v2 = INV ? make_float2(-u2.y, u2.x) : make_float2(u2.y, -u2.x);
    float2 v3 = cmul(u3, om3);
    float2 s02=cadd(t0,t2), d02=csub(t0,t2), s13=cadd(t1,t3), d13=csub(t1,t3);
    float2 jd = make_float2(-d13.y, d13.x);
    x[0] = cadd(s02, s13);
    x[4] = csub(s02, s13);
    x[2] = INV ? cadd(d02, jd) : csub(d02, jd);
    x[6] = INV ? csub(d02, jd) : cadd(d02, jd);
    float2 so=cadd(u0,v2), doo=csub(u0,v2), s13o=cadd(v1,v3), d13o=csub(v1,v3);
    float2 jdo = make_float2(-d13o.y, d13o.x);
    x[1] = cadd(so, s13o);
    x[5] = csub(so, s13o);
    x[3] = INV ? cadd(doo, jdo) : csub(doo, jdo);
    x[7] = INV ? csub(doo, jdo) : cadd(doo, jdo);
}

// Forward DIF butterfly at index idx (twiddle AFTER dft). wb = W_{8M}^(idx&(M-1)).
template<int MB>
__device__ __forceinline__ void bf_fwd(float2* __restrict__ buf, int idx, float2 wb)
{
    const int M = 1 << MB;
    const int j = idx & (M-1);
    const int base = ((idx >> MB) << (MB+3)) | j;
    float2 x[8];
    #pragma unroll
    for (int k = 0; k < 8; ++k) x[k] = buf[PH(base + (k<<MB))];
    dft8<false>(x);
    float2 w = wb;
    #pragma unroll
    for (int r = 1; r < 8; ++r) { x[r] = cmul(x[r], w); if (r < 7) w = cmul(w, wb); }
    #pragma unroll
    for (int k = 0; k < 8; ++k) buf[PH(base + (k<<MB))] = x[k];
}

// Inverse DIT butterfly at index idx (twiddle BEFORE dft). wb pre-conjugated.
template<int MB>
__device__ __forceinline__ void bf_inv(float2* __restrict__ buf, int idx, float2 wb)
{
    const int M = 1 << MB;
    const int j = idx & (M-1);
    const int base = ((idx >> MB) << (MB+3)) | j;
    float2 x[8];
    #pragma unroll
    for (int k = 0; k < 8; ++k) x[k] = buf[PH(base + (k<<MB))];
    float2 w = wb;
    #pragma unroll
    for (int r = 1; r < 8; ++r) { x[r] = cmul(x[r], w); if (r < 7) w = cmul(w, wb); }
    dft8<true>(x);
    #pragma unroll
    for (int k = 0; k < 8; ++k) buf[PH(base + (k<<MB))] = x[k];
}

// Lehmer code of stable argsort of (a,b,c), matching reference id formula.
__device__ __forceinline__ int permid(float a, float b, float c)
{
    int i0 = (a <= b) ? 1 : 0;
    int i1 = (a <= c) ? 1 : 0;
    int i2 = (b <= c) ? 1 : 0;
    int idx = (i0 << 2) | (i1 << 1) | i2;
    const unsigned LUT = (5u<<0)|(3u<<4)|(0u<<8)|(2u<<12)|(4u<<16)|(0u<<20)|(1u<<24)|(0u<<28);
    return (int)((LUT >> (idx*4)) & 0xFu);
}

__device__ __forceinline__ constexpr int qidx(int k, int l) { return k*(9-k)/2 + l; }

__global__ __launch_bounds__(NTHREADS, 3)
void tfmptf_kernel(const float* __restrict__ in, float* __restrict__ out)
{
    extern __shared__ char smraw[];
    Smem& sm = *reinterpret_cast<Smem*>(smraw);
    const int tid = threadIdx.x;
    const int bid = blockIdx.x;          // bid = b*64 + d
    const int d = bid & 63;
    const int b = bid >> 6;
    const int warp = tid >> 5;
    const int lane = tid & 31;

    // --- tables + hist zero ---
    float2 myw0 = __ldg(&g_tw512[tid]);
    float2 myw1 = __ldg(&g_tw512[tid + 256]);
    if (tid < 64) sm.t8[tid]  = __ldg(&g_t8[tid]);
    if (tid < 8)  sm.t64[tid] = __ldg(&g_t64[tid]);
    for (int i = tid; i < 8*36; i += NTHREADS) ((int*)sm.hist)[i] = 0;

    // --- forward stage 0 (M=512): gmem -> butterfly -> buf0; 2 butterflies ---
    const float* xin = in + ((long)b * TLEN) * 64 + d;
    #pragma unroll
    for (int h = 0; h < 2; ++h) {
        const int idx = tid + (h<<8);
        const float2 wb = h ? myw1 : myw0;
        float2 x[8];
        #pragma unroll
        for (int k = 0; k < 8; ++k)
            x[k] = make_float2(__ldg(&xin[(long)(idx + (k<<9)) * 64]), 0.0f);
        dft8<false>(x);
        float2 w = wb;
        #pragma unroll
        for (int r = 1; r < 8; ++r) { x[r] = cmul(x[r], w); if (r < 7) w = cmul(w, wb); }
        #pragma unroll
        for (int k = 0; k < 8; ++k) sm.buf0[PH(idx + (k<<9))] = x[k];
    }
    __syncthreads();

    // --- forward stages 1 (M=64), 2 (M=8); both butterflies share twiddle ---
    {
        float2 wb = sm.t8[tid & 63];
        bf_fwd<6>(sm.buf0, tid, wb);
        bf_fwd<6>(sm.buf0, tid + 256, wb);
    }
    __syncthreads();
    {
        float2 wb = sm.t64[tid & 7];
        bf_fwd<3>(sm.buf0, tid, wb);
        bf_fwd<3>(sm.buf0, tid + 256, wb);
    }
    __syncthreads();

    // --- fused: fwd stage 3 (trivial tw) + masks + inv stage 0 ---
    #pragma unroll
    for (int h = 0; h < 2; ++h) {
        const int idx = tid + (h<<8);
        const int base = idx << 3;
        float2 y[8];
        #pragma unroll
        for (int k = 0; k < 8; ++k) y[k] = sm.buf0[PH(base + k)];
        dft8<false>(y);
        if (idx == 0) sm.xnyq = y[4].x;          // pos 4 = rev(2048)
        #pragma unroll
        for (int k = 0; k < 8; ++k) sm.buf1[PH(base + k)] = y[k];  // park spectrum
        #pragma unroll
        for (int k = 0; k < 8; ++k) {
            float4 S = __ldg(&g_masks_br[base + k]);
            float2 Y = y[k];
            y[k] = make_float2(Y.x*S.x - Y.y*S.y, Y.x*S.y + Y.y*S.x);
        }
        dft8<true>(y);
        #pragma unroll
        for (int k = 0; k < 8; ++k) sm.buf0[PH(base + k)] = y[k];
        #pragma unroll
        for (int k = 0; k < 8; ++k) {
            float2 Y = sm.buf1[PH(base + k)];
            float sz = __ldg(&g_masks_br[base + k]).z;
            y[k] = make_float2(Y.x*sz, Y.y*sz);
        }
        dft8<true>(y);
        #pragma unroll
        for (int k = 0; k < 8; ++k) sm.buf1[PH(base + k)] = y[k];
    }
    __syncthreads();

    // --- inverse stages: L=64 (M=8), L=512 (M=64) ---
    {
        float2 wb = conj2(sm.t64[tid & 7]);
        bf_inv<3>(sm.buf0, tid, wb);
        bf_inv<3>(sm.buf0, tid + 256, wb);
        bf_inv<3>(sm.buf1, tid, wb);
        bf_inv<3>(sm.buf1, tid + 256, wb);
    }
    __syncthreads();
    {
        float2 wb = conj2(sm.t8[tid & 63]);
        bf_inv<6>(sm.buf0, tid, wb);
        bf_inv<6>(sm.buf0, tid + 256, wb);
        bf_inv<6>(sm.buf1, tid, wb);
        bf_inv<6>(sm.buf1, tid + 256, wb);
    }
    __syncthreads();

    // --- final inverse stage (L=4096, M=512): 4 butterflies ---
    #pragma unroll
    for (int h = 0; h < 2; ++h) {
        const int idx = tid + (h<<8);
        const float2 wb = conj2(h ? myw1 : myw0);
        #pragma unroll
        for (int bb = 0; bb < 2; ++bb) {
            float2* buf = bb ? sm.buf1 : sm.buf0;
            float2 x[8];
            #pragma unroll
            for (int k = 0; k < 8; ++k) x[k] = buf[PH(idx + (k<<9))];
            float2 w = wb;
            #pragma unroll
            for (int r = 1; r < 8; ++r) { x[r] = cmul(x[r], w); if (r < 7) w = cmul(w, wb); }
            dft8<true>(x);
            #pragma unroll
            for (int k = 0; k < 8; ++k) buf[PH(idx + (k<<9))] = x[k];
        }
    }

    // --- Nyquist rank-1 corrections ---
    const float xn = sm.xnyq * (1.0f/4096.0f);
    const float eg[3] = {
        0.49999813667341397f * xn,
        0.30309759854236545f * xn,
        0.06211314334918520f * xn
    };

    // --- correlation moments (own slots t = tid + 256m, parity = tid&1) ---
    float S[5]; float Q[15];
    #pragma unroll
    for (int i = 0; i < 5; ++i) S[i] = 0.f;
    #pragma unroll
    for (int i = 0; i < 15; ++i) Q[i] = 0.f;
    const float pe = (tid & 1) ? -1.f : 1.f;
    #pragma unroll
    for (int m = 0; m < 16; ++m) {
        int a = PH(tid + (m<<8));
        float2 z = sm.buf0[a];
        float m2 = sm.buf1[a].x;
        float e[5];
        float t;
        t = z.x + pe*eg[0]; e[0] = t*t;
        t = z.y + pe*eg[1]; e[1] = t*t;
        t = m2  + pe*eg[2]; e[2] = t*t;
        t = m2  - pe*eg[2]; e[3] = t*t;
        t = z.y - pe*eg[1]; e[4] = t*t;
        #pragma unroll
        for (int kk = 0; kk < 5; ++kk) {
            S[kk] += e[kk];
            #pragma unroll
            for (int l = kk; l < 5; ++l)
                Q[qidx(kk,l)] = fmaf(e[kk], e[l], Q[qidx(kk,l)]);
        }
    }
    {
        float vvv[20];
        #pragma unroll
        for (int j = 0; j < 5; ++j)  vvv[j]   = S[j];
        #pragma unroll
        for (int j = 0; j < 15; ++j) vvv[5+j] = Q[j];
        #pragma unroll
        for (int j = 0; j < 20; ++j)
            #pragma unroll
            for (int off = 16; off; off >>= 1)
                vvv[j] += __shfl_down_sync(0xffffffffu, vvv[j], off);
        if (lane == 0)
            #pragma unroll
            for (int j = 0; j < 20; ++j) sm.red[warp][j] = vvv[j];
    }
    __syncthreads();   // modes stores + red visible

    // --- sliding-window permutation transitions: 5 (mode,sign) passes, 16/thr ---
    {
        const int w0 = tid * 16;
        #pragma unroll
        for (int gg = 0; gg < 3; ++gg) {
            const int nsign = (gg == 0) ? 1 : 2;
            #pragma unroll
            for (int sv = 0; sv < 2; ++sv) {
                if (sv >= nsign) break;
                const float eps = (sv == 0) ? eg[gg] : -eg[gg];
                float vv[19];
                #pragma unroll
                for (int i = 0; i < 19; ++i) {
                    int e = w0 + i; e = (e < TLEN) ? e : (TLEN - 1);
                    int a = PH(e);
                    float m = (gg == 0) ? sm.buf0[a].x
                            : ((gg == 1) ? sm.buf0[a].y : sm.buf1[a].x);
                    vv[i] = m + (((w0 + i) & 1) ? -eps : eps);
                }
                int id[17];
                #pragma unroll
                for (int i = 0; i < 17; ++i)
                    id[i] = permid(vv[i], vv[i+1], vv[i+2]);
                #pragma unroll
                for (int i = 0; i < 16; ++i) {
                    bool valid = (w0 + i) < 4093;
                    int code = valid ? (id[i]*6 + id[i+1]) : 36;
                    unsigned grp = __match_any_sync(0xffffffffu, code);
                    if (valid && (int)(__ffs(grp) - 1) == lane)
                        atomicAdd(&sm.hist[warp][code], __popc(grp));
                }
            }
        }
    }
    __syncthreads();

    if (tid < 36) {
        int ctot = 0;
        #pragma unroll
        for (int w = 0; w < 8; ++w) ctot += sm.hist[w][tid];
        sm.cnt[tid] = ctot;
    }
    if (tid < 20) {
        float tot = 0.f;
        #pragma unroll
        for (int w = 0; w < 8; ++w) tot += sm.red[w][tid];
        sm.totals[tid] = tot;
    }
    __syncthreads();

    float* outbd = out + (long)bid * 46;
    if (tid < 36) {
        int pp = tid / 6;
        int rs = 0;
        #pragma unroll
        for (int qq = 0; qq < 6; ++qq) rs += sm.cnt[pp*6 + qq];
        float denom = rs ? (float)rs : 1.0f;
        outbd[tid] = (float)sm.cnt[tid] / denom;
    }
    if (tid == 0) {
        const float invT = 1.0f / 4096.0f;
        float cov[15];
        #pragma unroll
        for (int k = 0; k < 5; ++k)
            #pragma unroll
            for (int l = k; l < 5; ++l)
                cov[qidx(k,l)] = sm.totals[5 + qidx(k,l)]
                               - sm.totals[k]*sm.totals[l]*invT;
        float dstd[5];
        #pragma unroll
        for (int k = 0; k < 5; ++k) dstd[k] = sqrtf(fmaxf(cov[qidx(k,k)], 0.f));
        int oi = 36;
        #pragma unroll
        for (int k = 0; k < 5; ++k) {
            #pragma unroll
            for (int l = k+1; l < 5; ++l) {
                float den = dstd[k] * dstd[l];
                float r = (den > 0.f) ? cov[qidx(k,l)] / den : 0.f;
                r = fminf(1.f, fmaxf(-1.f, r));
                outbd[oi++] = r;
            }
        }
    }
}

extern "C" void kernel_launch(void* const* d_in, const int* in_sizes, int n_in,
                              void* d_out, int out_size)
{
    (void)in_sizes; (void)n_in; (void)out_size;
    const float* in = (const float*)d_in[0];
    float* out = (float*)d_out;
    init_tables<<<8, 512>>>();
    cudaFuncSetAttribute(tfmptf_kernel, cudaFuncAttributeMaxDynamicSharedMemorySize,
                         (int)sizeof(Smem));
    tfmptf_kernel<<<1024, NTHREADS, sizeof(Smem)>>>(in, out);
}

// round 12
// speedup vs baseline: 1.1196x; 1.1196x over previous
#include <cuda_runtime.h>

#define NTHREADS 512
#define TLEN 4096

// bank swizzle: conflict-free for strides 512/64/8/1 (verified per half-warp)
#define PH(e) ((e) ^ ((((unsigned)(e))>>3)&7u) ^ (((((unsigned)(e))>>6)&1u)<<3))

__device__ float2 g_masks01_br[TLEN]; // (S0,S1) at digit-reversed position, 1/4096 folded
__device__ float  g_masks2_br[TLEN];  // S2 at digit-reversed position, 1/4096 folded
__device__ float2 g_tw512[512];       // W4096^j
__device__ float2 g_t8[64];           // W4096^(8j)  = W512^j
__device__ float2 g_t64[8];           // W4096^(64j) = W64^j

struct __align__(16) Smem {
    float2 buf0[TLEN];     // Y1 path -> modes01 (natural, PH layout)
    float2 buf1[TLEN];     // spectrum park, then Y2 path -> mode2 in .x
    float2 t8[64];
    float2 t64[8];
    int    hist[8][36];
    float  red[16][20];
    float  totals[20];
    int    cnt[36];
    float  xnyq;
};

__device__ __forceinline__ float2 cadd(float2 a, float2 b){ return make_float2(a.x+b.x, a.y+b.y); }
__device__ __forceinline__ float2 csub(float2 a, float2 b){ return make_float2(a.x-b.x, a.y-b.y); }
__device__ __forceinline__ float2 cmul(float2 a, float2 b){
    return make_float2(fmaf(a.x,b.x,-a.y*b.y), fmaf(a.x,b.y, a.y*b.x));
}
__device__ __forceinline__ float2 conj2(float2 a){ return make_float2(a.x, -a.y); }

__global__ void init_tables()
{
    int j = blockIdx.x * blockDim.x + threadIdx.x;   // 0..4095
    float sv, cv;
    if (j < 512) {
        sincospif(-(float)j * (1.0f/2048.0f), &sv, &cv);  // -2pi j/4096
        g_tw512[j] = make_float2(cv, sv);
    }
    if (j < 64) {
        sincospif(-(float)j * (1.0f/256.0f), &sv, &cv);   // -2pi 8j/4096
        g_t8[j] = make_float2(cv, sv);
    }
    if (j < 8) {
        sincospif(-(float)j * (1.0f/32.0f), &sv, &cv);    // -2pi 64j/4096
        g_t64[j] = make_float2(cv, sv);
    }
    // frequency bin at digit-reversed position j (4 base-8 digits)
    int K = ((j&7)<<9) | (((j>>3)&7)<<6) | (((j>>6)&7)<<3) | ((j>>9)&7);
    float f = (float)((K < 2048) ? K : (K - 4096)) * (1.0f/4096.0f);
    const float h = 0.5f * (1.0f/4096.0f);
    float u;
    u = f + 0.5f; float a0 = expf(-12.5f*u*u);
    u = f - 0.5f; float a1 = expf(-12.5f*u*u);
    u = f - 0.3f; float b0 = expf(-12.5f*u*u);
    u = f + 0.3f; float b1 = expf(-12.5f*u*u);
    u = f - 0.1f; float c0 = expf(-12.5f*u*u);
    u = f + 0.1f; float c1 = expf(-12.5f*u*u);
    g_masks01_br[j] = make_float2(h*(a0+a1), h*(b0+b1));
    g_masks2_br[j]  = h*(c0+c1);
}

// In-place DFT-8: x[r] <- sum_n x[n] * W8^(+-rn)
template<bool INV>
__device__ __forceinline__ void dft8(float2 x[8])
{
    float2 t0=cadd(x[0],x[4]), t1=cadd(x[1],x[5]), t2=cadd(x[2],x[6]), t3=cadd(x[3],x[7]);
    float2 u0=csub(x[0],x[4]), u1=csub(x[1],x[5]), u2=csub(x[2],x[6]), u3=csub(x[3],x[7]);
    const float C8 = 0.70710678118654752f;
    const float2 om  = INV ? make_float2( C8,  C8) : make_float2( C8, -C8);
    const float2 om3 = INV ? make_float2(-C8,  C8) : make_float2(-C8, -C8);
    float2 v1 = cmul(u1, om);
    float2 v2 = INV ? make_float2(-u2.y, u2.x) : make_float2(u2.y, -u2.x);
    float2 v3 = cmul(u3, om3);
    float2 s02=cadd(t0,t2), d02=csub(t0,t2), s13=cadd(t1,t3), d13=csub(t1,t3);
    float2 jd = make_float2(-d13.y, d13.x);
    x[0] = cadd(s02, s13);
    x[4] = csub(s02, s13);
    x[2] = INV ? cadd(d02, jd) : csub(d02, jd);
    x[6] = INV ? csub(d02, jd) : cadd(d02, jd);
    float2 so=cadd(u0,v2), doo=csub(u0,v2), s13o=cadd(v1,v3), d13o=csub(v1,v3);
    float2 jdo = make_float2(-d13o.y, d13o.x);
    x[1] = cadd(so, s13o);
    x[5] = csub(so, s13o);
    x[3] = INV ? cadd(doo, jdo) : csub(doo, jdo);
    x[7] = INV ? csub(doo, jdo) : cadd(doo, jdo);
}

// In-place forward DIF stage, M = 2^MB; wb = W_L^j (L = 8M), twiddle AFTER dft.
template<int MB>
__device__ __forceinline__ void stage_fwd(float2* __restrict__ buf, int tid, float2 wb)
{
    const int M = 1 << MB;
    const int j = tid & (M-1);
    const int base = ((tid >> MB) << (MB+3)) | j;
    float2 x[8];
    #pragma unroll
    for (int k = 0; k < 8; ++k) x[k] = buf[PH(base + (k<<MB))];
    dft8<false>(x);
    float2 w = wb;
    #pragma unroll
    for (int r = 1; r < 8; ++r) { x[r] = cmul(x[r], w); if (r < 7) w = cmul(w, wb); }
    #pragma unroll
    for (int k = 0; k < 8; ++k) buf[PH(base + (k<<MB))] = x[k];
}

// In-place single-buffer inverse DIT stage, twiddle BEFORE dft. wb pre-conjugated.
template<int MB>
__device__ __forceinline__ void stage_inv(float2* __restrict__ buf, int tid, float2 wb)
{
    const int M = 1 << MB;
    const int j = tid & (M-1);
    const int base = ((tid >> MB) << (MB+3)) | j;
    float2 x[8];
    #pragma unroll
    for (int k = 0; k < 8; ++k) x[k] = buf[PH(base + (k<<MB))];
    float2 w = wb;
    #pragma unroll
    for (int r = 1; r < 8; ++r) { x[r] = cmul(x[r], w); if (r < 7) w = cmul(w, wb); }
    dft8<true>(x);
    #pragma unroll
    for (int k = 0; k < 8; ++k) buf[PH(base + (k<<MB))] = x[k];
}

// Lehmer code of stable argsort of (a,b,c), matching reference id formula.
__device__ __forceinline__ int permid(float a, float b, float c)
{
    int i0 = (a <= b) ? 1 : 0;
    int i1 = (a <= c) ? 1 : 0;
    int i2 = (b <= c) ? 1 : 0;
    int idx = (i0 << 2) | (i1 << 1) | i2;
    const unsigned LUT = (5u<<0)|(3u<<4)|(0u<<8)|(2u<<12)|(4u<<16)|(0u<<20)|(1u<<24)|(0u<<28);
    return (int)((LUT >> (idx*4)) & 0xFu);
}

__device__ __forceinline__ constexpr int qidx(int k, int l) { return k*(9-k)/2 + l; }

__global__ __launch_bounds__(NTHREADS, 3)
void tfmptf_kernel(const float* __restrict__ in, float* __restrict__ out)
{
    extern __shared__ char smraw[];
    Smem& sm = *reinterpret_cast<Smem*>(smraw);
    const int tid = threadIdx.x;
    const int bid = blockIdx.x;          // bid = b*64 + d
    const int d = bid & 63;
    const int b = bid >> 6;
    const int warp = tid >> 5;
    const int lane = tid & 31;

    // --- tables + hist zero (no barrier needed before stage 0: own-index use) ---
    float2 myw = __ldg(&g_tw512[tid]);
    if (tid < 64) sm.t8[tid]  = __ldg(&g_t8[tid]);
    if (tid < 8)  sm.t64[tid] = __ldg(&g_t64[tid]);
    for (int i = tid; i < 8*36; i += NTHREADS) ((int*)sm.hist)[i] = 0;

    // --- forward stage 0 (M=512): gmem -> butterfly -> buf0 ---
    const float* xin = in + ((long)b * TLEN) * 64 + d;
    {
        float2 x[8];
        #pragma unroll
        for (int k = 0; k < 8; ++k)
            x[k] = make_float2(__ldg(&xin[(long)(tid + (k<<9)) * 64]), 0.0f);
        dft8<false>(x);
        float2 w = myw;
        #pragma unroll
        for (int r = 1; r < 8; ++r) { x[r] = cmul(x[r], w); if (r < 7) w = cmul(w, myw); }
        #pragma unroll
        for (int k = 0; k < 8; ++k) sm.buf0[PH(tid + (k<<9))] = x[k];
    }
    __syncthreads();

    // --- forward stages 1 (M=64), 2 (M=8) ---
    stage_fwd<6>(sm.buf0, tid, sm.t8[tid & 63]);
    __syncthreads();
    stage_fwd<3>(sm.buf0, tid, sm.t64[tid & 7]);
    __syncthreads();

    // --- fused: fwd stage 3 (trivial tw) + masks + inv stage 0, one 8-array live ---
    {
        const int base = tid << 3;
        float2 y[8];
        #pragma unroll
        for (int k = 0; k < 8; ++k) y[k] = sm.buf0[PH(base + k)];
        dft8<false>(y);
        if (tid == 0) sm.xnyq = y[4].x;          // pos 4 = rev(2048)
        #pragma unroll
        for (int k = 0; k < 8; ++k) sm.buf1[PH(base + k)] = y[k];  // park spectrum
        // Y1 path
        #pragma unroll
        for (int k = 0; k < 8; ++k) {
            float2 S = __ldg(&g_masks01_br[base + k]);
            float2 Y = y[k];
            y[k] = make_float2(Y.x*S.x - Y.y*S.y, Y.x*S.y + Y.y*S.x);
        }
        dft8<true>(y);
        #pragma unroll
        for (int k = 0; k < 8; ++k) sm.buf0[PH(base + k)] = y[k];
        // Y2 path (reload parked spectrum; own slots, no barrier)
        #pragma unroll
        for (int k = 0; k < 8; ++k) {
            float2 Y = sm.buf1[PH(base + k)];
            float sz = __ldg(&g_masks2_br[base + k]);
            y[k] = make_float2(Y.x*sz, Y.y*sz);
        }
        dft8<true>(y);
        #pragma unroll
        for (int k = 0; k < 8; ++k) sm.buf1[PH(base + k)] = y[k];
    }
    __syncthreads();

    // --- inverse stages: L=64 (M=8), L=512 (M=64); single-buffer calls ---
    stage_inv<3>(sm.buf0, tid, conj2(sm.t64[tid & 7]));
    stage_inv<3>(sm.buf1, tid, conj2(sm.t64[tid & 7]));
    __syncthreads();
    stage_inv<6>(sm.buf0, tid, conj2(sm.t8[tid & 63]));
    stage_inv<6>(sm.buf1, tid, conj2(sm.t8[tid & 63]));
    __syncthreads();

    // --- final inverse stage (L=4096, M=512); one buffer at a time ---
    {
        float2 wb = conj2(myw);
        float2 x[8];
        #pragma unroll
        for (int k = 0; k < 8; ++k) x[k] = sm.buf0[PH(tid + (k<<9))];
        float2 w = wb;
        #pragma unroll
        for (int r = 1; r < 8; ++r) { x[r] = cmul(x[r], w); if (r < 7) w = cmul(w, wb); }
        dft8<true>(x);
        #pragma unroll
        for (int k = 0; k < 8; ++k) sm.buf0[PH(tid + (k<<9))] = x[k];
        #pragma unroll
        for (int k = 0; k < 8; ++k) x[k] = sm.buf1[PH(tid + (k<<9))];
        w = wb;
        #pragma unroll
        for (int r = 1; r < 8; ++r) { x[r] = cmul(x[r], w); if (r < 7) w = cmul(w, wb); }
        dft8<true>(x);
        #pragma unroll
        for (int k = 0; k < 8; ++k) sm.buf1[PH(tid + (k<<9))] = x[k];
    }

    // --- Nyquist rank-1 corrections ---
    const float xn = sm.xnyq * (1.0f/4096.0f);
    const float eg[3] = {
        0.49999813667341397f * xn,
        0.30309759854236545f * xn,
        0.06211314334918520f * xn
    };
    const float pe = (tid & 1) ? -1.f : 1.f;

    // --- correlation moments, pass 1: sums + diagonal (low reg pressure) ---
    float S[5], Qd[5];
    #pragma unroll
    for (int i = 0; i < 5; ++i) { S[i] = 0.f; Qd[i] = 0.f; }
    #pragma unroll
    for (int k = 0; k < 8; ++k) {
        int a = PH(tid + (k<<9));
        float2 z = sm.buf0[a];
        float m2 = sm.buf1[a].x;
        float e[5], t;
        t = z.x + pe*eg[0]; e[0] = t*t;
        t = z.y + pe*eg[1]; e[1] = t*t;
        t = m2  + pe*eg[2]; e[2] = t*t;
        t = m2  - pe*eg[2]; e[3] = t*t;
        t = z.y - pe*eg[1]; e[4] = t*t;
        #pragma unroll
        for (int kk = 0; kk < 5; ++kk) {
            S[kk] += e[kk];
            Qd[kk] = fmaf(e[kk], e[kk], Qd[kk]);
        }
    }
    // --- pass 2: off-diagonal products ---
    float Qo[10];
    #pragma unroll
    for (int i = 0; i < 10; ++i) Qo[i] = 0.f;
    #pragma unroll
    for (int k = 0; k < 8; ++k) {
        int a = PH(tid + (k<<9));
        float2 z = sm.buf0[a];
        float m2 = sm.buf1[a].x;
        float e[5], t;
        t = z.x + pe*eg[0]; e[0] = t*t;
        t = z.y + pe*eg[1]; e[1] = t*t;
        t = m2  + pe*eg[2]; e[2] = t*t;
        t = m2  - pe*eg[2]; e[3] = t*t;
        t = z.y - pe*eg[1]; e[4] = t*t;
        int oi = 0;
        #pragma unroll
        for (int kk = 0; kk < 5; ++kk)
            #pragma unroll
            for (int l = kk+1; l < 5; ++l)
                { Qo[oi] = fmaf(e[kk], e[l], Qo[oi]); ++oi; }
    }
    {
        float vvv[20];
        #pragma unroll
        for (int j = 0; j < 5; ++j) {
            vvv[j] = S[j];
            vvv[5 + qidx(j,j)] = Qd[j];
        }
        {
            int oi = 0;
            #pragma unroll
            for (int kk = 0; kk < 5; ++kk)
                #pragma unroll
                for (int l = kk+1; l < 5; ++l)
                    { vvv[5 + qidx(kk,l)] = Qo[oi]; ++oi; }
        }
        #pragma unroll
        for (int j = 0; j < 20; ++j)
            #pragma unroll
            for (int off = 16; off; off >>= 1)
                vvv[j] += __shfl_down_sync(0xffffffffu, vvv[j], off);
        if (lane == 0)
            #pragma unroll
            for (int j = 0; j < 20; ++j) sm.red[warp][j] = vvv[j];
    }
    __syncthreads();   // modes stores + red visible

    // --- sliding-window permutation transitions: loads hoisted out of sign loop ---
    {
        const int w0 = tid * 8;
        #pragma unroll
        for (int gg = 0; gg < 3; ++gg) {
            float mv[11];
            #pragma unroll
            for (int i = 0; i < 11; ++i) {
                int e = w0 + i; e = (e < TLEN) ? e : (TLEN - 1);
                int a = PH(e);
                mv[i] = (gg == 0) ? sm.buf0[a].x
                      : ((gg == 1) ? sm.buf0[a].y : sm.buf1[a].x);
            }
            const int nsign = (gg == 0) ? 1 : 2;
            #pragma unroll
            for (int sv = 0; sv < 2; ++sv) {
                if (sv >= nsign) break;
                const float eps = (sv == 0) ? eg[gg] : -eg[gg];
                float vv[11];
                #pragma unroll
                for (int i = 0; i < 11; ++i)
                    vv[i] = mv[i] + (((w0 + i) & 1) ? -eps : eps);
                int id[9];
                #pragma unroll
                for (int i = 0; i < 9; ++i)
                    id[i] = permid(vv[i], vv[i+1], vv[i+2]);
                #pragma unroll
                for (int i = 0; i < 8; ++i) {
                    bool valid = (w0 + i) < 4093;
                    int code = valid ? (id[i]*6 + id[i+1]) : 36;
                    unsigned grp = __match_any_sync(0xffffffffu, code);
                    if (valid && (int)(__ffs(grp) - 1) == lane)
                        atomicAdd(&sm.hist[warp >> 1][code], __popc(grp));
                }
            }
        }
    }
    __syncthreads();

    if (tid < 36) {
        int ctot = 0;
        #pragma unroll
        for (int w = 0; w < 8; ++w) ctot += sm.hist[w][tid];
        sm.cnt[tid] = ctot;
    }
    if (tid < 20) {
        float tot = 0.f;
        #pragma unroll
        for (int w = 0; w < 16; ++w) tot += sm.red[w][tid];
        sm.totals[tid] = tot;
    }
    __syncthreads();

    float* outbd = out + (long)bid * 46;
    if (tid < 36) {
        int pp = tid / 6;
        int rs = 0;
        #pragma unroll
        for (int qq = 0; qq < 6; ++qq) rs += sm.cnt[pp*6 + qq];
        float denom = rs ? (float)rs : 1.0f;
        outbd[tid] = (float)sm.cnt[tid] / denom;
    }
    if (tid == 0) {
        const float invT = 1.0f / 4096.0f;
        float cov[15];
        #pragma unroll
        for (int k = 0; k < 5; ++k)
            #pragma unroll
            for (int l = k; l < 5; ++l)
                cov[qidx(k,l)] = sm.totals[5 + qidx(k,l)]
                               - sm.totals[k]*sm.totals[l]*invT;
        float dstd[5];
        #pragma unroll
        for (int k = 0; k < 5; ++k) dstd[k] = sqrtf(fmaxf(cov[qidx(k,k)], 0.f));
        int oi = 36;
        #pragma unroll
        for (int k = 0; k < 5; ++k) {
            #pragma unroll
            for (int l = k+1; l < 5; ++l) {
                float den = dstd[k] * dstd[l];
                float r = (den > 0.f) ? cov[qidx(k,l)] / den : 0.f;
                r = fminf(1.f, fmaxf(-1.f, r));
                outbd[oi++] = r;
            }
        }
    }
}

extern "C" void kernel_launch(void* const* d_in, const int* in_sizes, int n_in,
                              void* d_out, int out_size)
{
    (void)in_sizes; (void)n_in; (void)out_size;
    const float* in = (const float*)d_in[0];
    float* out = (float*)d_out;
    init_tables<<<8, 512>>>();
    cudaFuncSetAttribute(tfmptf_kernel, cudaFuncAttributeMaxDynamicSharedMemorySize,
                         (int)sizeof(Smem));
    tfmptf_kernel<<<1024, NTHREADS, sizeof(Smem)>>>(in, out);
}

// round 13
// speedup vs baseline: 1.1199x; 1.0003x over previous
#include <cuda_runtime.h>

#define NTHREADS 512
#define TLEN 4096

// bank swizzle: conflict-free for strides 512/64/8/1 (verified per half-warp)
#define PH(e) ((e) ^ ((((unsigned)(e))>>3)&7u) ^ (((((unsigned)(e))>>6)&1u)<<3))

__device__ float2 g_masks01_br[TLEN]; // (S0,S1) at digit-reversed position, 1/4096 folded
__device__ float  g_masks2_br[TLEN];  // S2 at digit-reversed position, 1/4096 folded
__device__ float2 g_tw512[512];       // W4096^j
__device__ float2 g_t8[64];           // W4096^(8j)  = W512^j
__device__ float2 g_t64[8];           // W4096^(64j) = W64^j

struct __align__(16) Smem {
    float2 buf0[TLEN];     // Y1 path -> modes01 (natural, PH layout)
    float2 buf1[TLEN];     // spectrum park, then Y2 path -> mode2 in .x
    float2 t8[64];
    float2 t64[8];
    int    hist[8][36];
    float  red[16][20];
    float  totals[20];
    int    cnt[36];
    float  xnyq;
};

__device__ __forceinline__ float2 cadd(float2 a, float2 b){ return make_float2(a.x+b.x, a.y+b.y); }
__device__ __forceinline__ float2 csub(float2 a, float2 b){ return make_float2(a.x-b.x, a.y-b.y); }
__device__ __forceinline__ float2 cmul(float2 a, float2 b){
    return make_float2(fmaf(a.x,b.x,-a.y*b.y), fmaf(a.x,b.y, a.y*b.x));
}
__device__ __forceinline__ float2 conj2(float2 a){ return make_float2(a.x, -a.y); }

__global__ void init_tables()
{
    int j = blockIdx.x * blockDim.x + threadIdx.x;   // 0..4095
    float sv, cv;
    if (j < 512) {
        sincospif(-(float)j * (1.0f/2048.0f), &sv, &cv);  // -2pi j/4096
        g_tw512[j] = make_float2(cv, sv);
    }
    if (j < 64) {
        sincospif(-(float)j * (1.0f/256.0f), &sv, &cv);   // -2pi 8j/4096
        g_t8[j] = make_float2(cv, sv);
    }
    if (j < 8) {
        sincospif(-(float)j * (1.0f/32.0f), &sv, &cv);    // -2pi 64j/4096
        g_t64[j] = make_float2(cv, sv);
    }
    // frequency bin at digit-reversed position j (4 base-8 digits)
    int K = ((j&7)<<9) | (((j>>3)&7)<<6) | (((j>>6)&7)<<3) | ((j>>9)&7);
    float f = (float)((K < 2048) ? K : (K - 4096)) * (1.0f/4096.0f);
    const float h = 0.5f * (1.0f/4096.0f);
    float u;
    u = f + 0.5f; float a0 = expf(-12.5f*u*u);
    u = f - 0.5f; float a1 = expf(-12.5f*u*u);
    u = f - 0.3f; float b0 = expf(-12.5f*u*u);
    u = f + 0.3f; float b1 = expf(-12.5f*u*u);
    u = f - 0.1f; float c0 = expf(-12.5f*u*u);
    u = f + 0.1f; float c1 = expf(-12.5f*u*u);
    g_masks01_br[j] = make_float2(h*(a0+a1), h*(b0+b1));
    g_masks2_br[j]  = h*(c0+c1);
}

// In-place DFT-8: x[r] <- sum_n x[n] * W8^(+-rn)
template<bool INV>
__device__ __forceinline__ void dft8(float2 x[8])
{
    float2 t0=cadd(x[0],x[4]), t1=cadd(x[1],x[5]), t2=cadd(x[2],x[6]), t3=cadd(x[3],x[7]);
    float2 u0=csub(x[0],x[4]), u1=csub(x[1],x[5]), u2=csub(x[2],x[6]), u3=csub(x[3],x[7]);
    const float C8 = 0.70710678118654752f;
    const float2 om  = INV ? make_float2( C8,  C8) : make_float2( C8, -C8);
    const float2 om3 = INV ? make_float2(-C8,  C8) : make_float2(-C8, -C8);
    float2 v1 = cmul(u1, om);
    float2 v2 = INV ? make_float2(-u2.y, u2.x) : make_float2(u2.y, -u2.x);
    float2 v3 = cmul(u3, om3);
    float2 s02=cadd(t0,t2), d02=csub(t0,t2), s13=cadd(t1,t3), d13=csub(t1,t3);
    float2 jd = make_float2(-d13.y, d13.x);
    x[0] = cadd(s02, s13);
    x[4] = csub(s02, s13);
    x[2] = INV ? cadd(d02, jd) : csub(d02, jd);
    x[6] = INV ? csub(d02, jd) : cadd(d02, jd);
    float2 so=cadd(u0,v2), doo=csub(u0,v2), s13o=cadd(v1,v3), d13o=csub(v1,v3);
    float2 jdo = make_float2(-d13o.y, d13o.x);
    x[1] = cadd(so, s13o);
    x[5] = csub(so, s13o);
    x[3] = INV ? cadd(doo, jdo) : csub(doo, jdo);
    x[7] = INV ? csub(doo, jdo) : cadd(doo, jdo);
}

// In-place forward DIF stage, M = 2^MB; wb = W_L^j (L = 8M), twiddle AFTER dft.
template<int MB>
__device__ __forceinline__ void stage_fwd(float2* __restrict__ buf, int tid, float2 wb)
{
    const int M = 1 << MB;
    const int j = tid & (M-1);
    const int base = ((tid >> MB) << (MB+3)) | j;
    float2 x[8];
    #pragma unroll
    for (int k = 0; k < 8; ++k) x[k] = buf[PH(base + (k<<MB))];
    dft8<false>(x);
    float2 w = wb;
    #pragma unroll
    for (int r = 1; r < 8; ++r) { x[r] = cmul(x[r], w); if (r < 7) w = cmul(w, wb); }
    #pragma unroll
    for (int k = 0; k < 8; ++k) buf[PH(base + (k<<MB))] = x[k];
}

// In-place single-buffer inverse DIT stage, twiddle BEFORE dft. wb pre-conjugated.
template<int MB>
__device__ __forceinline__ void stage_inv(float2* __restrict__ buf, int tid, float2 wb)
{
    const int M = 1 << MB;
    const int j = tid & (M-1);
    const int base = ((tid >> MB) << (MB+3)) | j;
    float2 x[8];
    #pragma unroll
    for (int k = 0; k < 8; ++k) x[k] = buf[PH(base + (k<<MB))];
    float2 w = wb;
    #pragma unroll
    for (int r = 1; r < 8; ++r) { x[r] = cmul(x[r], w); if (r < 7) w = cmul(w, wb); }
    dft8<true>(x);
    #pragma unroll
    for (int k = 0; k < 8; ++k) buf[PH(base + (k<<MB))] = x[k];
}

// Lehmer id from comparison bits: i0=(a<=b), i1=(a<=c), i2=(b<=c)
__device__ __forceinline__ int permlut(int i0, int i1, int i2)
{
    int idx = (i0 << 2) | (i1 << 1) | i2;
    const unsigned LUT = (5u<<0)|(3u<<4)|(0u<<8)|(2u<<12)|(4u<<16)|(0u<<20)|(1u<<24)|(0u<<28);
    return (int)((LUT >> (idx*4)) & 0xFu);
}

__device__ __forceinline__ constexpr int qidx(int k, int l) { return k*(9-k)/2 + l; }

__global__ __launch_bounds__(NTHREADS, 3)
void tfmptf_kernel(const float* __restrict__ in, float* __restrict__ out)
{
    extern __shared__ char smraw[];
    Smem& sm = *reinterpret_cast<Smem*>(smraw);
    const int tid = threadIdx.x;
    const int bid = blockIdx.x;          // bid = b*64 + d
    const int d = bid & 63;
    const int b = bid >> 6;
    const int warp = tid >> 5;
    const int lane = tid & 31;

    // --- tables + hist zero (no barrier needed before stage 0: own-index use) ---
    float2 myw = __ldg(&g_tw512[tid]);
    if (tid < 64) sm.t8[tid]  = __ldg(&g_t8[tid]);
    if (tid < 8)  sm.t64[tid] = __ldg(&g_t64[tid]);
    for (int i = tid; i < 8*36; i += NTHREADS) ((int*)sm.hist)[i] = 0;

    // --- forward stage 0 (M=512): gmem -> butterfly -> buf0 ---
    const float* xin = in + ((long)b * TLEN) * 64 + d;
    {
        float2 x[8];
        #pragma unroll
        for (int k = 0; k < 8; ++k)
            x[k] = make_float2(__ldg(&xin[(long)(tid + (k<<9)) * 64]), 0.0f);
        dft8<false>(x);
        float2 w = myw;
        #pragma unroll
        for (int r = 1; r < 8; ++r) { x[r] = cmul(x[r], w); if (r < 7) w = cmul(w, myw); }
        #pragma unroll
        for (int k = 0; k < 8; ++k) sm.buf0[PH(tid + (k<<9))] = x[k];
    }
    __syncthreads();

    // --- forward stages 1 (M=64), 2 (M=8) ---
    stage_fwd<6>(sm.buf0, tid, sm.t8[tid & 63]);
    __syncthreads();
    stage_fwd<3>(sm.buf0, tid, sm.t64[tid & 7]);
    __syncthreads();

    // --- fused: fwd stage 3 (trivial tw) + masks + inv stage 0, one 8-array live ---
    {
        const int base = tid << 3;
        float2 y[8];
        #pragma unroll
        for (int k = 0; k < 8; ++k) y[k] = sm.buf0[PH(base + k)];
        dft8<false>(y);
        if (tid == 0) sm.xnyq = y[4].x;          // pos 4 = rev(2048)
        #pragma unroll
        for (int k = 0; k < 8; ++k) sm.buf1[PH(base + k)] = y[k];  // park spectrum
        // Y1 path
        #pragma unroll
        for (int k = 0; k < 8; ++k) {
            float2 S = __ldg(&g_masks01_br[base + k]);
            float2 Y = y[k];
            y[k] = make_float2(Y.x*S.x - Y.y*S.y, Y.x*S.y + Y.y*S.x);
        }
        dft8<true>(y);
        #pragma unroll
        for (int k = 0; k < 8; ++k) sm.buf0[PH(base + k)] = y[k];
        // Y2 path (reload parked spectrum; own slots, no barrier)
        #pragma unroll
        for (int k = 0; k < 8; ++k) {
            float2 Y = sm.buf1[PH(base + k)];
            float sz = __ldg(&g_masks2_br[base + k]);
            y[k] = make_float2(Y.x*sz, Y.y*sz);
        }
        dft8<true>(y);
        #pragma unroll
        for (int k = 0; k < 8; ++k) sm.buf1[PH(base + k)] = y[k];
    }
    __syncthreads();

    // --- inverse stages: L=64 (M=8), L=512 (M=64); single-buffer calls ---
    stage_inv<3>(sm.buf0, tid, conj2(sm.t64[tid & 7]));
    stage_inv<3>(sm.buf1, tid, conj2(sm.t64[tid & 7]));
    __syncthreads();
    stage_inv<6>(sm.buf0, tid, conj2(sm.t8[tid & 63]));
    stage_inv<6>(sm.buf1, tid, conj2(sm.t8[tid & 63]));
    __syncthreads();

    // --- final inverse stage (L=4096, M=512); one buffer at a time ---
    {
        float2 wb = conj2(myw);
        float2 x[8];
        #pragma unroll
        for (int k = 0; k < 8; ++k) x[k] = sm.buf0[PH(tid + (k<<9))];
        float2 w = wb;
        #pragma unroll
        for (int r = 1; r < 8; ++r) { x[r] = cmul(x[r], w); if (r < 7) w = cmul(w, wb); }
        dft8<true>(x);
        #pragma unroll
        for (int k = 0; k < 8; ++k) sm.buf0[PH(tid + (k<<9))] = x[k];
        #pragma unroll
        for (int k = 0; k < 8; ++k) x[k] = sm.buf1[PH(tid + (k<<9))];
        w = wb;
        #pragma unroll
        for (int r = 1; r < 8; ++r) { x[r] = cmul(x[r], w); if (r < 7) w = cmul(w, wb); }
        dft8<true>(x);
        #pragma unroll
        for (int k = 0; k < 8; ++k) sm.buf1[PH(tid + (k<<9))] = x[k];
    }

    // --- Nyquist rank-1 corrections ---
    const float xn = sm.xnyq * (1.0f/4096.0f);
    const float eg[3] = {
        0.49999813667341397f * xn,
        0.30309759854236545f * xn,
        0.06211314334918520f * xn
    };
    const float pe = (tid & 1) ? -1.f : 1.f;

    // --- correlation moments, pass 1: sums + diagonal (low reg pressure) ---
    float S[5], Qd[5];
    #pragma unroll
    for (int i = 0; i < 5; ++i) { S[i] = 0.f; Qd[i] = 0.f; }
    #pragma unroll
    for (int k = 0; k < 8; ++k) {
        int a = PH(tid + (k<<9));
        float2 z = sm.buf0[a];
        float m2 = sm.buf1[a].x;
        float e[5], t;
        t = z.x + pe*eg[0]; e[0] = t*t;
        t = z.y + pe*eg[1]; e[1] = t*t;
        t = m2  + pe*eg[2]; e[2] = t*t;
        t = m2  - pe*eg[2]; e[3] = t*t;
        t = z.y - pe*eg[1]; e[4] = t*t;
        #pragma unroll
        for (int kk = 0; kk < 5; ++kk) {
            S[kk] += e[kk];
            Qd[kk] = fmaf(e[kk], e[kk], Qd[kk]);
        }
    }
    // --- pass 2: off-diagonal products ---
    float Qo[10];
    #pragma unroll
    for (int i = 0; i < 10; ++i) Qo[i] = 0.f;
    #pragma unroll
    for (int k = 0; k < 8; ++k) {
        int a = PH(tid + (k<<9));
        float2 z = sm.buf0[a];
        float m2 = sm.buf1[a].x;
        float e[5], t;
        t = z.x + pe*eg[0]; e[0] = t*t;
        t = z.y + pe*eg[1]; e[1] = t*t;
        t = m2  + pe*eg[2]; e[2] = t*t;
        t = m2  - pe*eg[2]; e[3] = t*t;
        t = z.y - pe*eg[1]; e[4] = t*t;
        int oi = 0;
        #pragma unroll
        for (int kk = 0; kk < 5; ++kk)
            #pragma unroll
            for (int l = kk+1; l < 5; ++l)
                { Qo[oi] = fmaf(e[kk], e[l], Qo[oi]); ++oi; }
    }
    {
        float vvv[20];
        #pragma unroll
        for (int j = 0; j < 5; ++j) {
            vvv[j] = S[j];
            vvv[5 + qidx(j,j)] = Qd[j];
        }
        {
            int oi = 0;
            #pragma unroll
            for (int kk = 0; kk < 5; ++kk)
                #pragma unroll
                for (int l = kk+1; l < 5; ++l)
                    { vvv[5 + qidx(kk,l)] = Qo[oi]; ++oi; }
        }
        #pragma unroll
        for (int j = 0; j < 20; ++j)
            #pragma unroll
            for (int off = 16; off; off >>= 1)
                vvv[j] += __shfl_down_sync(0xffffffffu, vvv[j], off);
        if (lane == 0)
            #pragma unroll
            for (int j = 0; j < 20; ++j) sm.red[warp][j] = vvv[j];
    }
    __syncthreads();   // modes stores + red visible

    // --- sliding-window permutation transitions, diff-based (low reg pressure) ---
    // w0 even => vv[i] = mv[i] + (-1)^i*eps. Comparisons:
    //   (vv[i]<=vv[i+2])  : eps cancels -> skip bit, shared across signs
    //   (vv[i]<=vv[i+1])  : adj[i] <= T_i,  T_i = (i odd ? +e2 : -e2), e2 = 2*eps
    //   (vv[i+1]<=vv[i+2]): adj[i+1] <= -T_i
    {
        const int w0 = tid * 8;
        #pragma unroll
        for (int gg = 0; gg < 3; ++gg) {
            float adj[10];
            unsigned skipb = 0;
            {
                float m0, m1, m2v;
                int e0 = (w0 < TLEN) ? w0 : (TLEN-1);
                int e1 = (w0+1 < TLEN) ? (w0+1) : (TLEN-1);
                int a0 = PH(e0), a1 = PH(e1);
                m0 = (gg == 0) ? sm.buf0[a0].x : ((gg == 1) ? sm.buf0[a0].y : sm.buf1[a0].x);
                m1 = (gg == 0) ? sm.buf0[a1].x : ((gg == 1) ? sm.buf0[a1].y : sm.buf1[a1].x);
                #pragma unroll
                for (int i = 0; i < 9; ++i) {
                    int e = w0 + i + 2; e = (e < TLEN) ? e : (TLEN - 1);
                    int a = PH(e);
                    m2v = (gg == 0) ? sm.buf0[a].x : ((gg == 1) ? sm.buf0[a].y : sm.buf1[a].x);
                    adj[i] = m0 - m1;
                    if (m0 <= m2v) skipb |= (1u << i);
                    m0 = m1; m1 = m2v;
                }
                adj[9] = m0 - m1;
            }
            const int nsign = (gg == 0) ? 1 : 2;
            #pragma unroll
            for (int sv = 0; sv < 2; ++sv) {
                if (sv >= nsign) break;
                const float e2 = ((sv == 0) ? 2.f : -2.f) * eg[gg];
                int prev = permlut((adj[0] <= -e2) ? 1 : 0,
                                   (int)(skipb & 1u),
                                   (adj[1] <= e2) ? 1 : 0);
                #pragma unroll
                for (int i = 0; i < 8; ++i) {
                    const float Ti = ((i + 1) & 1) ? e2 : -e2;
                    int cur = permlut((adj[i+1] <= Ti) ? 1 : 0,
                                      (int)((skipb >> (i+1)) & 1u),
                                      (adj[i+2] <= -Ti) ? 1 : 0);
                    bool valid = (w0 + i) < 4093;
                    int code = valid ? (prev*6 + cur) : 36;
                    unsigned grp = __match_any_sync(0xffffffffu, code);
                    if (valid && (int)(__ffs(grp) - 1) == lane)
                        atomicAdd(&sm.hist[warp >> 1][code], __popc(grp));
                    prev = cur;
                }
            }
        }
    }
    __syncthreads();

    if (tid < 36) {
        int ctot = 0;
        #pragma unroll
        for (int w = 0; w < 8; ++w) ctot += sm.hist[w][tid];
        sm.cnt[tid] = ctot;
    }
    if (tid < 20) {
        float tot = 0.f;
        #pragma unroll
        for (int w = 0; w < 16; ++w) tot += sm.red[w][tid];
        sm.totals[tid] = tot;
    }
    __syncthreads();

    float* outbd = out + (long)bid * 46;
    if (tid < 36) {
        int pp = tid / 6;
        int rs = 0;
        #pragma unroll
        for (int qq = 0; qq < 6; ++qq) rs += sm.cnt[pp*6 + qq];
        float denom = rs ? (float)rs : 1.0f;
        outbd[tid] = (float)sm.cnt[tid] / denom;
    }
    if (tid == 0) {
        const float invT = 1.0f / 4096.0f;
        float cov[15];
        #pragma unroll
        for (int k = 0; k < 5; ++k)
            #pragma unroll
            for (int l = k; l < 5; ++l)
                cov[qidx(k,l)] = sm.totals[5 + qidx(k,l)]
                               - sm.totals[k]*sm.totals[l]*invT;
        float dstd[5];
        #pragma unroll
        for (int k = 0; k < 5; ++k) dstd[k] = sqrtf(fmaxf(cov[qidx(k,k)], 0.f));
        int oi = 36;
        #pragma unroll
        for (int k = 0; k < 5; ++k) {
            #pragma unroll
            for (int l = k+1; l < 5; ++l) {
                float den = dstd[k] * dstd[l];
                float r = (den > 0.f) ? cov[qidx(k,l)] / den : 0.f;
                r = fminf(1.f, fmaxf(-1.f, r));
                outbd[oi++] = r;
            }
        }
    }
}

extern "C" void kernel_launch(void* const* d_in, const int* in_sizes, int n_in,
                              void* d_out, int out_size)
{
    (void)in_sizes; (void)n_in; (void)out_size;
    const float* in = (const float*)d_in[0];
    float* out = (float*)d_out;
    init_tables<<<8, 512>>>();
    cudaFuncSetAttribute(tfmptf_kernel, cudaFuncAttributeMaxDynamicSharedMemorySize,
                         (int)sizeof(Smem));
    tfmptf_kernel<<<1024, NTHREADS, sizeof(Smem)>>>(in, out);
}

// round 14
// speedup vs baseline: 1.2783x; 1.1415x over previous
#include <cuda_runtime.h>

#define NTHREADS 512
#define TLEN 4096

// bank swizzle: conflict-free for strides 512/64/8/1 (verified per half-warp)
#define PH(e) ((e) ^ ((((unsigned)(e))>>3)&7u) ^ (((((unsigned)(e))>>6)&1u)<<3))

__device__ float  g_xT[16*64*4096];   // transposed input [b][d][t] (16 MB scratch)
__device__ float2 g_masks01_br[TLEN]; // (S0,S1) at digit-reversed position, 1/4096 folded
__device__ float  g_masks2_br[TLEN];  // S2 at digit-reversed position, 1/4096 folded
__device__ float2 g_tw512[512];       // W4096^j
__device__ float2 g_t8[64];           // W4096^(8j)  = W512^j
__device__ float2 g_t64[8];           // W4096^(64j) = W64^j

struct __align__(16) Smem {
    float2 buf0[TLEN];     // Y1 path -> modes01 (natural, PH layout)
    float2 buf1[TLEN];     // spectrum park, then Y2 path -> mode2 in .x
    float2 t8[64];
    float2 t64[8];
    int    hist[8][36];
    float  red[16][20];
    float  totals[20];
    int    cnt[36];
    float  xnyq;
};

__device__ __forceinline__ float2 cadd(float2 a, float2 b){ return make_float2(a.x+b.x, a.y+b.y); }
__device__ __forceinline__ float2 csub(float2 a, float2 b){ return make_float2(a.x-b.x, a.y-b.y); }
__device__ __forceinline__ float2 cmul(float2 a, float2 b){
    return make_float2(fmaf(a.x,b.x,-a.y*b.y), fmaf(a.x,b.y, a.y*b.x));
}
__device__ __forceinline__ float2 conj2(float2 a){ return make_float2(a.x, -a.y); }

__global__ void init_tables()
{
    int j = blockIdx.x * blockDim.x + threadIdx.x;   // 0..4095
    float sv, cv;
    if (j < 512) {
        sincospif(-(float)j * (1.0f/2048.0f), &sv, &cv);  // -2pi j/4096
        g_tw512[j] = make_float2(cv, sv);
    }
    if (j < 64) {
        sincospif(-(float)j * (1.0f/256.0f), &sv, &cv);   // -2pi 8j/4096
        g_t8[j] = make_float2(cv, sv);
    }
    if (j < 8) {
        sincospif(-(float)j * (1.0f/32.0f), &sv, &cv);    // -2pi 64j/4096
        g_t64[j] = make_float2(cv, sv);
    }
    // frequency bin at digit-reversed position j (4 base-8 digits)
    int K = ((j&7)<<9) | (((j>>3)&7)<<6) | (((j>>6)&7)<<3) | ((j>>9)&7);
    float f = (float)((K < 2048) ? K : (K - 4096)) * (1.0f/4096.0f);
    const float h = 0.5f * (1.0f/4096.0f);
    float u;
    u = f + 0.5f; float a0 = expf(-12.5f*u*u);
    u = f - 0.5f; float a1 = expf(-12.5f*u*u);
    u = f - 0.3f; float b0 = expf(-12.5f*u*u);
    u = f + 0.3f; float b1 = expf(-12.5f*u*u);
    u = f - 0.1f; float c0 = expf(-12.5f*u*u);
    u = f + 0.1f; float c1 = expf(-12.5f*u*u);
    g_masks01_br[j] = make_float2(h*(a0+a1), h*(b0+b1));
    g_masks2_br[j]  = h*(c0+c1);
}

// Tiled transpose: in[b][t][d] -> g_xT[b][d][t]. Fully coalesced both sides.
__global__ void transpose_in(const float* __restrict__ in)
{
    __shared__ float tile[32][33];
    const int b  = blockIdx.z;
    const int t0 = blockIdx.x * 32;
    const int d0 = blockIdx.y * 32;
    const int tx = threadIdx.x, ty = threadIdx.y;
    #pragma unroll
    for (int i = 0; i < 4; ++i) {
        int t = t0 + ty + i*8;
        tile[ty + i*8][tx] = in[((long)b*4096 + t)*64 + (d0 + tx)];
    }
    __syncthreads();
    #pragma unroll
    for (int i = 0; i < 4; ++i) {
        int dd = d0 + ty + i*8;
        g_xT[((long)b*64 + dd)*4096 + (t0 + tx)] = tile[tx][ty + i*8];
    }
}

// In-place DFT-8: x[r] <- sum_n x[n] * W8^(+-rn)
template<bool INV>
__device__ __forceinline__ void dft8(float2 x[8])
{
    float2 t0=cadd(x[0],x[4]), t1=cadd(x[1],x[5]), t2=cadd(x[2],x[6]), t3=cadd(x[3],x[7]);
    float2 u0=csub(x[0],x[4]), u1=csub(x[1],x[5]), u2=csub(x[2],x[6]), u3=csub(x[3],x[7]);
    const float C8 = 0.70710678118654752f;
    const float2 om  = INV ? make_float2( C8,  C8) : make_float2( C8, -C8);
    const float2 om3 = INV ? make_float2(-C8,  C8) : make_float2(-C8, -C8);
    float2 v1 = cmul(u1, om);
    float2 v2 = INV ? make_float2(-u2.y, u2.x) : make_float2(u2.y, -u2.x);
    float2 v3 = cmul(u3, om3);
    float2 s02=cadd(t0,t2), d02=csub(t0,t2), s13=cadd(t1,t3), d13=csub(t1,t3);
    float2 jd = make_float2(-d13.y, d13.x);
    x[0] = cadd(s02, s13);
    x[4] = csub(s02, s13);
    x[2] = INV ? cadd(d02, jd) : csub(d02, jd);
    x[6] = INV ? csub(d02, jd) : cadd(d02, jd);
    float2 so=cadd(u0,v2), doo=csub(u0,v2), s13o=cadd(v1,v3), d13o=csub(v1,v3);
    float2 jdo = make_float2(-d13o.y, d13o.x);
    x[1] = cadd(so, s13o);
    x[5] = csub(so, s13o);
    x[3] = INV ? cadd(doo, jdo) : csub(doo, jdo);
    x[7] = INV ? csub(doo, jdo) : cadd(doo, jdo);
}

// Log-depth twiddle powers: w[r] = wb^(r+1), depth 3 instead of 6.
__device__ __forceinline__ void twpow(float2 wb, float2 w[7])
{
    w[0] = wb;
    w[1] = cmul(wb, wb);       // w2
    w[2] = cmul(wb, w[1]);     // w3
    w[3] = cmul(w[1], w[1]);   // w4
    w[4] = cmul(w[1], w[2]);   // w5
    w[5] = cmul(w[2], w[2]);   // w6
    w[6] = cmul(w[2], w[3]);   // w7
}

// In-place forward DIF stage, M = 2^MB; wb = W_L^j (L = 8M), twiddle AFTER dft.
template<int MB>
__device__ __forceinline__ void stage_fwd(float2* __restrict__ buf, int tid, float2 wb)
{
    const int M = 1 << MB;
    const int j = tid & (M-1);
    const int base = ((tid >> MB) << (MB+3)) | j;
    float2 x[8];
    #pragma unroll
    for (int k = 0; k < 8; ++k) x[k] = buf[PH(base + (k<<MB))];
    dft8<false>(x);
    float2 w[7];
    twpow(wb, w);
    #pragma unroll
    for (int r = 1; r < 8; ++r) x[r] = cmul(x[r], w[r-1]);
    #pragma unroll
    for (int k = 0; k < 8; ++k) buf[PH(base + (k<<MB))] = x[k];
}

// In-place single-buffer inverse DIT stage, twiddle BEFORE dft. wb pre-conjugated.
template<int MB>
__device__ __forceinline__ void stage_inv(float2* __restrict__ buf, int tid, float2 wb)
{
    const int M = 1 << MB;
    const int j = tid & (M-1);
    const int base = ((tid >> MB) << (MB+3)) | j;
    float2 x[8];
    #pragma unroll
    for (int k = 0; k < 8; ++k) x[k] = buf[PH(base + (k<<MB))];
    float2 w[7];
    twpow(wb, w);
    #pragma unroll
    for (int r = 1; r < 8; ++r) x[r] = cmul(x[r], w[r-1]);
    dft8<true>(x);
    #pragma unroll
    for (int k = 0; k < 8; ++k) buf[PH(base + (k<<MB))] = x[k];
}

// Lehmer id from comparison bits: i0=(a<=b), i1=(a<=c), i2=(b<=c)
__device__ __forceinline__ int permlut(int i0, int i1, int i2)
{
    int idx = (i0 << 2) | (i1 << 1) | i2;
    const unsigned LUT = (5u<<0)|(3u<<4)|(0u<<8)|(2u<<12)|(4u<<16)|(0u<<20)|(1u<<24)|(0u<<28);
    return (int)((LUT >> (idx*4)) & 0xFu);
}

__device__ __forceinline__ constexpr int qidx(int k, int l) { return k*(9-k)/2 + l; }

__global__ __launch_bounds__(NTHREADS, 3)
void tfmptf_kernel(const float* __restrict__ in, float* __restrict__ out)
{
    extern __shared__ char smraw[];
    Smem& sm = *reinterpret_cast<Smem*>(smraw);
    const int tid = threadIdx.x;
    const int bid = blockIdx.x;          // bid = b*64 + d
    const int warp = tid >> 5;
    const int lane = tid & 31;
    (void)in;

    // --- tables + hist zero (no barrier needed before stage 0: own-index use) ---
    float2 myw = __ldg(&g_tw512[tid]);
    if (tid < 64) sm.t8[tid]  = __ldg(&g_t8[tid]);
    if (tid < 8)  sm.t64[tid] = __ldg(&g_t64[tid]);
    for (int i = tid; i < 8*36; i += NTHREADS) ((int*)sm.hist)[i] = 0;

    // --- forward stage 0 (M=512): coalesced gmem -> butterfly -> buf0 ---
    const float* xrow = g_xT + (size_t)bid * TLEN;
    {
        float2 x[8];
        #pragma unroll
        for (int k = 0; k < 8; ++k)
            x[k] = make_float2(__ldg(&xrow[tid + (k<<9)]), 0.0f);
        dft8<false>(x);
        float2 w[7];
        twpow(myw, w);
        #pragma unroll
        for (int r = 1; r < 8; ++r) x[r] = cmul(x[r], w[r-1]);
        #pragma unroll
        for (int k = 0; k < 8; ++k) sm.buf0[PH(tid + (k<<9))] = x[k];
    }
    __syncthreads();

    // --- forward stages 1 (M=64), 2 (M=8) ---
    stage_fwd<6>(sm.buf0, tid, sm.t8[tid & 63]);
    __syncthreads();
    stage_fwd<3>(sm.buf0, tid, sm.t64[tid & 7]);
    __syncthreads();

    // --- fused: fwd stage 3 (trivial tw) + masks + inv stage 0, one 8-array live ---
    {
        const int base = tid << 3;
        float2 y[8];
        #pragma unroll
        for (int k = 0; k < 8; ++k) y[k] = sm.buf0[PH(base + k)];
        dft8<false>(y);
        if (tid == 0) sm.xnyq = y[4].x;          // pos 4 = rev(2048)
        #pragma unroll
        for (int k = 0; k < 8; ++k) sm.buf1[PH(base + k)] = y[k];  // park spectrum
        // Y1 path
        #pragma unroll
        for (int k = 0; k < 8; ++k) {
            float2 S = __ldg(&g_masks01_br[base + k]);
            float2 Y = y[k];
            y[k] = make_float2(Y.x*S.x - Y.y*S.y, Y.x*S.y + Y.y*S.x);
        }
        dft8<true>(y);
        #pragma unroll
        for (int k = 0; k < 8; ++k) sm.buf0[PH(base + k)] = y[k];
        // Y2 path (reload parked spectrum; own slots, no barrier)
        #pragma unroll
        for (int k = 0; k < 8; ++k) {
            float2 Y = sm.buf1[PH(base + k)];
            float sz = __ldg(&g_masks2_br[base + k]);
            y[k] = make_float2(Y.x*sz, Y.y*sz);
        }
        dft8<true>(y);
        #pragma unroll
        for (int k = 0; k < 8; ++k) sm.buf1[PH(base + k)] = y[k];
    }
    __syncthreads();

    // --- inverse stages: L=64 (M=8), L=512 (M=64); single-buffer calls ---
    stage_inv<3>(sm.buf0, tid, conj2(sm.t64[tid & 7]));
    stage_inv<3>(sm.buf1, tid, conj2(sm.t64[tid & 7]));
    __syncthreads();
    stage_inv<6>(sm.buf0, tid, conj2(sm.t8[tid & 63]));
    stage_inv<6>(sm.buf1, tid, conj2(sm.t8[tid & 63]));
    __syncthreads();

    // --- final inverse stage (L=4096, M=512); one buffer at a time ---
    {
        float2 wb = conj2(myw);
        float2 w[7];
        twpow(wb, w);
        float2 x[8];
        #pragma unroll
        for (int k = 0; k < 8; ++k) x[k] = sm.buf0[PH(tid + (k<<9))];
        #pragma unroll
        for (int r = 1; r < 8; ++r) x[r] = cmul(x[r], w[r-1]);
        dft8<true>(x);
        #pragma unroll
        for (int k = 0; k < 8; ++k) sm.buf0[PH(tid + (k<<9))] = x[k];
        #pragma unroll
        for (int k = 0; k < 8; ++k) x[k] = sm.buf1[PH(tid + (k<<9))];
        #pragma unroll
        for (int r = 1; r < 8; ++r) x[r] = cmul(x[r], w[r-1]);
        dft8<true>(x);
        #pragma unroll
        for (int k = 0; k < 8; ++k) sm.buf1[PH(tid + (k<<9))] = x[k];
    }

    // --- Nyquist rank-1 corrections ---
    const float xn = sm.xnyq * (1.0f/4096.0f);
    const float eg[3] = {
        0.49999813667341397f * xn,
        0.30309759854236545f * xn,
        0.06211314334918520f * xn
    };
    const float pe = (tid & 1) ? -1.f : 1.f;

    // --- correlation moments, pass 1: sums + diagonal (low reg pressure) ---
    float S[5], Qd[5];
    #pragma unroll
    for (int i = 0; i < 5; ++i) { S[i] = 0.f; Qd[i] = 0.f; }
    #pragma unroll
    for (int k = 0; k < 8; ++k) {
        int a = PH(tid + (k<<9));
        float2 z = sm.buf0[a];
        float m2 = sm.buf1[a].x;
        float e[5], t;
        t = z.x + pe*eg[0]; e[0] = t*t;
        t = z.y + pe*eg[1]; e[1] = t*t;
        t = m2  + pe*eg[2]; e[2] = t*t;
        t = m2  - pe*eg[2]; e[3] = t*t;
        t = z.y - pe*eg[1]; e[4] = t*t;
        #pragma unroll
        for (int kk = 0; kk < 5; ++kk) {
            S[kk] += e[kk];
            Qd[kk] = fmaf(e[kk], e[kk], Qd[kk]);
        }
    }
    // --- pass 2: off-diagonal products ---
    float Qo[10];
    #pragma unroll
    for (int i = 0; i < 10; ++i) Qo[i] = 0.f;
    #pragma unroll
    for (int k = 0; k < 8; ++k) {
        int a = PH(tid + (k<<9));
        float2 z = sm.buf0[a];
        float m2 = sm.buf1[a].x;
        float e[5], t;
        t = z.x + pe*eg[0]; e[0] = t*t;
        t = z.y + pe*eg[1]; e[1] = t*t;
        t = m2  + pe*eg[2]; e[2] = t*t;
        t = m2  - pe*eg[2]; e[3] = t*t;
        t = z.y - pe*eg[1]; e[4] = t*t;
        int oi = 0;
        #pragma unroll
        for (int kk = 0; kk < 5; ++kk)
            #pragma unroll
            for (int l = kk+1; l < 5; ++l)
                { Qo[oi] = fmaf(e[kk], e[l], Qo[oi]); ++oi; }
    }
    {
        float vvv[20];
        #pragma unroll
        for (int j = 0; j < 5; ++j) {
            vvv[j] = S[j];
            vvv[5 + qidx(j,j)] = Qd[j];
        }
        {
            int oi = 0;
            #pragma unroll
            for (int kk = 0; kk < 5; ++kk)
                #pragma unroll
                for (int l = kk+1; l < 5; ++l)
                    { vvv[5 + qidx(kk,l)] = Qo[oi]; ++oi; }
        }
        #pragma unroll
        for (int j = 0; j < 20; ++j)
            #pragma unroll
            for (int off = 16; off; off >>= 1)
                vvv[j] += __shfl_down_sync(0xffffffffu, vvv[j], off);
        if (lane == 0)
            #pragma unroll
            for (int j = 0; j < 20; ++j) sm.red[warp][j] = vvv[j];
    }
    __syncthreads();   // modes stores + red visible

    // --- sliding-window permutation transitions, diff-based (low reg pressure) ---
    {
        const int w0 = tid * 8;
        #pragma unroll
        for (int gg = 0; gg < 3; ++gg) {
            float adj[10];
            unsigned skipb = 0;
            {
                float m0, m1, m2v;
                int e0 = (w0 < TLEN) ? w0 : (TLEN-1);
                int e1 = (w0+1 < TLEN) ? (w0+1) : (TLEN-1);
                int a0 = PH(e0), a1 = PH(e1);
                m0 = (gg == 0) ? sm.buf0[a0].x : ((gg == 1) ? sm.buf0[a0].y : sm.buf1[a0].x);
                m1 = (gg == 0) ? sm.buf0[a1].x : ((gg == 1) ? sm.buf0[a1].y : sm.buf1[a1].x);
                #pragma unroll
                for (int i = 0; i < 9; ++i) {
                    int e = w0 + i + 2; e = (e < TLEN) ? e : (TLEN - 1);
                    int a = PH(e);
                    m2v = (gg == 0) ? sm.buf0[a].x : ((gg == 1) ? sm.buf0[a].y : sm.buf1[a].x);
                    adj[i] = m0 - m1;
                    if (m0 <= m2v) skipb |= (1u << i);
                    m0 = m1; m1 = m2v;
                }
                adj[9] = m0 - m1;
            }
            const int nsign = (gg == 0) ? 1 : 2;
            #pragma unroll
            for (int sv = 0; sv < 2; ++sv) {
                if (sv >= nsign) break;
                const float e2 = ((sv == 0) ? 2.f : -2.f) * eg[gg];
                int prev = permlut((adj[0] <= -e2) ? 1 : 0,
                                   (int)(skipb & 1u),
                                   (adj[1] <= e2) ? 1 : 0);
                #pragma unroll
                for (int i = 0; i < 8; ++i) {
                    const float Ti = ((i + 1) & 1) ? e2 : -e2;
                    int cur = permlut((adj[i+1] <= Ti) ? 1 : 0,
                                      (int)((skipb >> (i+1)) & 1u),
                                      (adj[i+2] <= -Ti) ? 1 : 0);
                    bool valid = (w0 + i) < 4093;
                    int code = valid ? (prev*6 + cur) : 36;
                    unsigned grp = __match_any_sync(0xffffffffu, code);
                    if (valid && (int)(__ffs(grp) - 1) == lane)
                        atomicAdd(&sm.hist[warp >> 1][code], __popc(grp));
                    prev = cur;
                }
            }
        }
    }
    __syncthreads();

    if (tid < 36) {
        int ctot = 0;
        #pragma unroll
        for (int w = 0; w < 8; ++w) ctot += sm.hist[w][tid];
        sm.cnt[tid] = ctot;
    }
    if (tid < 20) {
        float tot = 0.f;
        #pragma unroll
        for (int w = 0; w < 16; ++w) tot += sm.red[w][tid];
        sm.totals[tid] = tot;
    }
    __syncthreads();

    float* outbd = out + (long)bid * 46;
    if (tid < 36) {
        int pp = tid / 6;
        int rs = 0;
        #pragma unroll
        for (int qq = 0; qq < 6; ++qq) rs += sm.cnt[pp*6 + qq];
        float denom = rs ? (float)rs : 1.0f;
        outbd[tid] = (float)sm.cnt[tid] / denom;
    }
    if (tid == 0) {
        const float invT = 1.0f / 4096.0f;
        float cov[15];
        #pragma unroll
        for (int k = 0; k < 5; ++k)
            #pragma unroll
            for (int l = k; l < 5; ++l)
                cov[qidx(k,l)] = sm.totals[5 + qidx(k,l)]
                               - sm.totals[k]*sm.totals[l]*invT;
        float dstd[5];
        #pragma unroll
        for (int k = 0; k < 5; ++k) dstd[k] = sqrtf(fmaxf(cov[qidx(k,k)], 0.f));
        int oi = 36;
        #pragma unroll
        for (int k = 0; k < 5; ++k) {
            #pragma unroll
            for (int l = k+1; l < 5; ++l) {
                float den = dstd[k] * dstd[l];
                float r = (den > 0.f) ? cov[qidx(k,l)] / den : 0.f;
                r = fminf(1.f, fmaxf(-1.f, r));
                outbd[oi++] = r;
            }
        }
    }
}

extern "C" void kernel_launch(void* const* d_in, const int* in_sizes, int n_in,
                              void* d_out, int out_size)
{
    (void)in_sizes; (void)n_in; (void)out_size;
    const float* in = (const float*)d_in[0];
    float* out = (float*)d_out;
    init_tables<<<8, 512>>>();
    transpose_in<<<dim3(128, 2, 16), dim3(32, 8)>>>(in);
    cudaFuncSetAttribute(tfmptf_kernel, cudaFuncAttributeMaxDynamicSharedMemorySize,
                         (int)sizeof(Smem));
    tfmptf_kernel<<<1024, NTHREADS, sizeof(Smem)>>>(in, out);
}